// round 2
// baseline (speedup 1.0000x reference)
#include <cuda_runtime.h>
#include <math_constants.h>

#define NQ   4096
#define NK   4096
#define FDIM 256
#define RADIUS2 9.0f
#define MAXN 128   // per-warp capacity (expected ~14 over 512 keys)

// Scratch (no allocation allowed)
__device__ float g_q[NQ * FDIM];
__device__ float g_k[NK * FDIM];
__device__ float g_v[NK * FDIM];
__device__ float g_att[NQ * FDIM];

// ---------------------------------------------------------------------------
// C[M,256] = A[M,256] @ W[256,256]^T + b.  64x64 tile, BK=16, 256 thr, 4x4/thr.
// ---------------------------------------------------------------------------
__device__ __forceinline__ void gemm_body(const float* __restrict__ A,
                                          const float* __restrict__ W,
                                          const float* __restrict__ b,
                                          float* __restrict__ C)
{
    __shared__ float As[16][65];
    __shared__ float Ws[16][65];

    const int tid = threadIdx.x;
    const int m0 = blockIdx.x * 64;
    const int n0 = blockIdx.y * 64;

    const int row = tid >> 2;
    const int kc  = (tid & 3) * 4;
    const int ty  = tid >> 4;
    const int tx  = tid & 15;

    float acc[4][4] = {};

    for (int kt = 0; kt < 256; kt += 16) {
        float4 av = *(const float4*)(A + (m0 + row) * 256 + kt + kc);
        float4 wv = *(const float4*)(W + (n0 + row) * 256 + kt + kc);
        As[kc + 0][row] = av.x; As[kc + 1][row] = av.y;
        As[kc + 2][row] = av.z; As[kc + 3][row] = av.w;
        Ws[kc + 0][row] = wv.x; Ws[kc + 1][row] = wv.y;
        Ws[kc + 2][row] = wv.z; Ws[kc + 3][row] = wv.w;
        __syncthreads();

        #pragma unroll
        for (int k = 0; k < 16; k++) {
            float a[4], w[4];
            #pragma unroll
            for (int i = 0; i < 4; i++) a[i] = As[k][ty * 4 + i];
            #pragma unroll
            for (int j = 0; j < 4; j++) w[j] = Ws[k][tx * 4 + j];
            #pragma unroll
            for (int i = 0; i < 4; i++)
                #pragma unroll
                for (int j = 0; j < 4; j++)
                    acc[i][j] = fmaf(a[i], w[j], acc[i][j]);
        }
        __syncthreads();
    }

    #pragma unroll
    for (int i = 0; i < 4; i++)
        #pragma unroll
        for (int j = 0; j < 4; j++) {
            int n = n0 + tx * 4 + j;
            C[(m0 + ty * 4 + i) * 256 + n] = acc[i][j] + b[n];
        }
}

// Fused Q/K/V projection: blockIdx.z selects which GEMM. One launch, 768 CTAs.
__global__ void gemm_qkv_kernel(const float* __restrict__ curf,
                                const float* __restrict__ histf,
                                const float* __restrict__ Wq, const float* __restrict__ bq, float* __restrict__ Cq,
                                const float* __restrict__ Wk, const float* __restrict__ bk, float* __restrict__ Ck,
                                const float* __restrict__ Wv, const float* __restrict__ bv, float* __restrict__ Cv)
{
    const float *A, *W, *b; float *C;
    if (blockIdx.z == 0)      { A = curf;  W = Wq; b = bq; C = Cq; }
    else if (blockIdx.z == 1) { A = histf; W = Wk; b = bk; C = Ck; }
    else                      { A = histf; W = Wv; b = bv; C = Cv; }
    gemm_body(A, W, b, C);
}

__global__ void gemm_bias_kernel(const float* __restrict__ A,
                                 const float* __restrict__ W,
                                 const float* __restrict__ b,
                                 float* __restrict__ C)
{
    gemm_body(A, W, b, C);
}

// ---------------------------------------------------------------------------
// Sparse masked attention, batched 32-neighbors-at-a-time.
// One CTA per query; warp = head, lane = head-dim.
// ---------------------------------------------------------------------------
__global__ void attn_kernel(const float* __restrict__ cq,
                            const float* __restrict__ ck,
                            float* __restrict__ out)
{
    const int qi   = blockIdx.x;
    const int tid  = threadIdx.x;
    const int warp = tid >> 5;
    const int lane = tid & 31;

    __shared__ int nbr[8][MAXN];
    __shared__ int cnt[8];
    __shared__ int offs[9];
    __shared__ int list[8 * MAXN];

    const float qx = cq[3 * qi + 0];
    const float qy = cq[3 * qi + 1];
    const float qz = cq[3 * qi + 2];

    // Phase 1: ballot-compact neighbor scan (deterministic, ascending)
    int c = 0;
    const int base0 = warp * 512;
    for (int base = base0; base < base0 + 512; base += 32) {
        int j = base + lane;
        float dx = qx - ck[3 * j + 0];
        float dy = qy - ck[3 * j + 1];
        float dz = qz - ck[3 * j + 2];
        bool pass = (dx * dx + dy * dy + dz * dz) <= RADIUS2;
        unsigned mk = __ballot_sync(0xffffffffu, pass);
        if (pass) {
            int pos = c + __popc(mk & ((1u << lane) - 1u));
            if (pos < MAXN) nbr[warp][pos] = j;
        }
        c += __popc(mk);
    }
    if (lane == 0) cnt[warp] = (c < MAXN) ? c : MAXN;
    __syncthreads();

    if (tid == 0) {
        int o = 0;
        #pragma unroll
        for (int w = 0; w < 8; w++) { offs[w] = o; o += cnt[w]; }
        offs[8] = o;
    }
    __syncthreads();

    // merge per-warp lists into one unified list
    {
        const int n = cnt[warp], o = offs[warp];
        for (int i = lane; i < n; i += 32) list[o + i] = nbr[warp][i];
    }
    __syncthreads();

    // Phase 2: chunked online softmax. 32 neighbors per chunk.
    const float qv = g_q[qi * 256 + tid];
    const float* kbase = g_k + tid;      // + ji*256 per neighbor
    const float* vbase = g_v + tid;
    const int ntot = offs[8];

    float m = -CUDART_INF_F, l = 0.0f, acc = 0.0f;

    for (int base = 0; base < ntot; base += 32) {
        const int nb = min(32, ntot - base);

        // partial products: part[i] = q[lane] * k[j_i][lane]  (coalesced loads)
        float part[32];
        #pragma unroll
        for (int i = 0; i < 32; i++) {
            if (i < nb) {
                int ji = list[base + i];             // LDS broadcast
                part[i] = qv * kbase[ji * 256];
            } else {
                part[i] = 0.0f;
            }
        }

        // transpose-reduce: 31 shuffles -> lane L holds dot for neighbor base+L
        #pragma unroll
        for (int off = 16; off > 0; off >>= 1) {
            #pragma unroll
            for (int i = 0; i < 16; i++) {
                if (i < off) {
                    float snd = (lane & off) ? part[i] : part[i + off];
                    float kp  = (lane & off) ? part[i + off] : part[i];
                    part[i] = kp + __shfl_xor_sync(0xffffffffu, snd, off);
                }
            }
        }

        float s = (lane < nb) ? part[0] * 0.17677669529663687f : -CUDART_INF_F;

        // chunk max + softmax update
        float cm = s;
        #pragma unroll
        for (int off = 16; off; off >>= 1)
            cm = fmaxf(cm, __shfl_xor_sync(0xffffffffu, cm, off));
        float newm = fmaxf(m, cm);
        float cr = __expf(m - newm);                 // 0 on first chunk
        float e  = (lane < nb) ? __expf(s - newm) : 0.0f;
        float sum = e;
        #pragma unroll
        for (int off = 16; off; off >>= 1)
            sum += __shfl_xor_sync(0xffffffffu, sum, off);
        l = l * cr + sum;
        acc *= cr;
        m = newm;

        // AV accumulation
        #pragma unroll
        for (int i = 0; i < 32; i++) {
            if (i < nb) {
                float ei = __shfl_sync(0xffffffffu, e, i);
                int ji = list[base + i];
                acc = fmaf(ei, vbase[ji * 256], acc);
            }
        }
    }
    out[qi * 256 + tid] = acc / l;
}

// ---------------------------------------------------------------------------
extern "C" void kernel_launch(void* const* d_in, const int* in_sizes, int n_in,
                              void* d_out, int out_size)
{
    const float* cur_f  = (const float*)d_in[0];
    const float* hist_f = (const float*)d_in[1];
    const float* cur_c  = (const float*)d_in[2];
    const float* hist_c = (const float*)d_in[3];
    const float* Wq = (const float*)d_in[4];
    const float* bq = (const float*)d_in[5];
    const float* Wk = (const float*)d_in[6];
    const float* bk = (const float*)d_in[7];
    const float* Wv = (const float*)d_in[8];
    const float* bv = (const float*)d_in[9];
    const float* Wo = (const float*)d_in[10];
    const float* bo = (const float*)d_in[11];
    float* out = (float*)d_out;

    float *pq, *pk, *pv, *patt;
    cudaGetSymbolAddress((void**)&pq,   g_q);
    cudaGetSymbolAddress((void**)&pk,   g_k);
    cudaGetSymbolAddress((void**)&pv,   g_v);
    cudaGetSymbolAddress((void**)&patt, g_att);

    dim3 gqkv(NQ / 64, FDIM / 64, 3);
    dim3 gg(NQ / 64, FDIM / 64);

    gemm_qkv_kernel<<<gqkv, 256>>>(cur_f, hist_f,
                                   Wq, bq, pq,
                                   Wk, bk, pk,
                                   Wv, bv, pv);

    attn_kernel<<<NQ, 256>>>(cur_c, hist_c, patt);

    gemm_bias_kernel<<<gg, 256>>>(patt, Wo, bo, out);
}

// round 3
// speedup vs baseline: 1.7599x; 1.7599x over previous
#include <cuda_runtime.h>
#include <math_constants.h>

#define NQ   4096
#define NK   4096
#define FDIM 256
#define RADIUS2 9.0f
#define MAXN 128

__device__ float g_q[NQ * FDIM];
__device__ float g_k[NK * FDIM];
__device__ float g_v[NK * FDIM];
__device__ float g_att[NQ * FDIM];

// ---------------------------------------------------------------------------
// C[M,256] = A[M,256] @ W[256,256]^T + b.  64x64 tile, BK=16, 256 thr, 4x4/thr.
// Smem padded to 68 floats/row so per-thread 4-col slices are 16B aligned.
// ---------------------------------------------------------------------------
__device__ __forceinline__ void gemm_body(const float* __restrict__ A,
                                          const float* __restrict__ W,
                                          const float* __restrict__ b,
                                          float* __restrict__ C)
{
    __shared__ float As[16][68];
    __shared__ float Ws[16][68];

    const int tid = threadIdx.x;
    const int m0 = blockIdx.x * 64;
    const int n0 = blockIdx.y * 64;

    const int row = tid >> 2;
    const int kc  = (tid & 3) * 4;
    const int ty  = tid >> 4;
    const int tx  = tid & 15;

    float acc[4][4] = {};

    for (int kt = 0; kt < 256; kt += 16) {
        float4 av = *(const float4*)(A + (m0 + row) * 256 + kt + kc);
        float4 wv = *(const float4*)(W + (n0 + row) * 256 + kt + kc);
        As[kc + 0][row] = av.x; As[kc + 1][row] = av.y;
        As[kc + 2][row] = av.z; As[kc + 3][row] = av.w;
        Ws[kc + 0][row] = wv.x; Ws[kc + 1][row] = wv.y;
        Ws[kc + 2][row] = wv.z; Ws[kc + 3][row] = wv.w;
        __syncthreads();

        #pragma unroll
        for (int k = 0; k < 16; k++) {
            float4 a = *(const float4*)&As[k][ty * 4];
            float4 w = *(const float4*)&Ws[k][tx * 4];
            float av4[4] = {a.x, a.y, a.z, a.w};
            float wv4[4] = {w.x, w.y, w.z, w.w};
            #pragma unroll
            for (int i = 0; i < 4; i++)
                #pragma unroll
                for (int j = 0; j < 4; j++)
                    acc[i][j] = fmaf(av4[i], wv4[j], acc[i][j]);
        }
        __syncthreads();
    }

    #pragma unroll
    for (int i = 0; i < 4; i++) {
        float4 o = make_float4(acc[i][0] + b[n0 + tx * 4 + 0],
                               acc[i][1] + b[n0 + tx * 4 + 1],
                               acc[i][2] + b[n0 + tx * 4 + 2],
                               acc[i][3] + b[n0 + tx * 4 + 3]);
        *(float4*)(C + (m0 + ty * 4 + i) * 256 + n0 + tx * 4) = o;
    }
}

__global__ void __launch_bounds__(256)
gemm_qkv_kernel(const float* __restrict__ curf,
                const float* __restrict__ histf,
                const float* __restrict__ Wq, const float* __restrict__ bq, float* __restrict__ Cq,
                const float* __restrict__ Wk, const float* __restrict__ bk, float* __restrict__ Ck,
                const float* __restrict__ Wv, const float* __restrict__ bv, float* __restrict__ Cv)
{
    const float *A, *W, *b; float *C;
    if (blockIdx.z == 0)      { A = curf;  W = Wq; b = bq; C = Cq; }
    else if (blockIdx.z == 1) { A = histf; W = Wk; b = bk; C = Ck; }
    else                      { A = histf; W = Wv; b = bv; C = Cv; }
    gemm_body(A, W, b, C);
}

__global__ void __launch_bounds__(256)
gemm_bias_kernel(const float* __restrict__ A,
                 const float* __restrict__ W,
                 const float* __restrict__ b,
                 float* __restrict__ C)
{
    gemm_body(A, W, b, C);
}

// ---------------------------------------------------------------------------
// Sparse masked attention. One CTA per query, warp = head.
// Phase 2: 8 lanes per neighbor (float4/lane), 4 neighbors per warp pass.
// ---------------------------------------------------------------------------
__global__ void __launch_bounds__(256)
attn_kernel(const float* __restrict__ cq,
            const float* __restrict__ ck,
            float* __restrict__ out)
{
    const int qi   = blockIdx.x;
    const int tid  = threadIdx.x;
    const int warp = tid >> 5;
    const int lane = tid & 31;

    __shared__ int nbr[8][MAXN];
    __shared__ int cnt[8];
    __shared__ int offs[9];
    __shared__ int list[8 * MAXN];

    const float qx = cq[3 * qi + 0];
    const float qy = cq[3 * qi + 1];
    const float qz = cq[3 * qi + 2];

    // Phase 1: ballot-compact neighbor scan (deterministic, ascending)
    int c = 0;
    const int base0 = warp * 512;
    for (int base = base0; base < base0 + 512; base += 32) {
        int j = base + lane;
        float dx = qx - ck[3 * j + 0];
        float dy = qy - ck[3 * j + 1];
        float dz = qz - ck[3 * j + 2];
        bool pass = (dx * dx + dy * dy + dz * dz) <= RADIUS2;
        unsigned mk = __ballot_sync(0xffffffffu, pass);
        if (pass) {
            int pos = c + __popc(mk & ((1u << lane) - 1u));
            if (pos < MAXN) nbr[warp][pos] = j;
        }
        c += __popc(mk);
    }
    if (lane == 0) cnt[warp] = (c < MAXN) ? c : MAXN;
    __syncthreads();

    if (tid == 0) {
        int o = 0;
        #pragma unroll
        for (int w = 0; w < 8; w++) { offs[w] = o; o += cnt[w]; }
        offs[8] = o;
    }
    __syncthreads();

    {
        const int n = cnt[warp], o = offs[warp];
        for (int i = lane; i < n; i += 32) list[o + i] = nbr[warp][i];
    }
    __syncthreads();

    // Phase 2
    const int head = warp;
    const int sub  = lane >> 3;          // neighbor slot 0..3 within pass
    const int dq   = (lane & 7) * 4;     // dim offset (float4) within head
    const int ntot = offs[8];

    const float4 qv = *(const float4*)(g_q + qi * 256 + head * 32 + dq);
    const float* kb = g_k + head * 32 + dq;
    const float* vb = g_v + head * 32 + dq;

    float m = -CUDART_INF_F, l = 0.0f;
    float4 acc = make_float4(0.f, 0.f, 0.f, 0.f);

    for (int base = 0; base < ntot; base += 4) {
        const int nb = ntot - base;            // >= 1
        int g = sub;
        if (g > nb - 1) g = nb - 1;            // clamp: duplicate last (masked below)
        const int j = list[base + g];

        const float4 kv = *(const float4*)(kb + j * 256);
        float p = qv.x * kv.x;
        p = fmaf(qv.y, kv.y, p);
        p = fmaf(qv.z, kv.z, p);
        p = fmaf(qv.w, kv.w, p);
        p += __shfl_xor_sync(0xffffffffu, p, 1);
        p += __shfl_xor_sync(0xffffffffu, p, 2);
        p += __shfl_xor_sync(0xffffffffu, p, 4);
        float s = p * 0.17677669529663687f;    // 1/sqrt(32)

        float s0 = __shfl_sync(0xffffffffu, s, 0);
        float s1 = __shfl_sync(0xffffffffu, s, 8);
        float s2 = __shfl_sync(0xffffffffu, s, 16);
        float s3 = __shfl_sync(0xffffffffu, s, 24);
        if (nb < 4) {                           // mask padded slots
            if (nb <= 1) s1 = -CUDART_INF_F;
            if (nb <= 2) s2 = -CUDART_INF_F;
            if (nb <= 3) s3 = -CUDART_INF_F;
        }

        float cm = fmaxf(fmaxf(s0, s1), fmaxf(s2, s3));
        float nm = fmaxf(m, cm);
        float cr = __expf(m - nm);              // 0 on first pass
        float e0 = __expf(s0 - nm);
        float e1 = __expf(s1 - nm);
        float e2 = __expf(s2 - nm);
        float e3 = __expf(s3 - nm);
        l = fmaf(l, cr, e0 + e1 + e2 + e3);
        m = nm;

        float eg = (sub == 0) ? e0 : (sub == 1) ? e1 : (sub == 2) ? e2 : e3;

        const float4 vv = *(const float4*)(vb + j * 256);
        acc.x = fmaf(acc.x, cr, eg * vv.x);
        acc.y = fmaf(acc.y, cr, eg * vv.y);
        acc.z = fmaf(acc.z, cr, eg * vv.z);
        acc.w = fmaf(acc.w, cr, eg * vv.w);
    }

    // cross-group reduction: sum the 4 neighbor-slot partials per dim
    #pragma unroll
    for (int off = 8; off <= 16; off <<= 1) {
        acc.x += __shfl_xor_sync(0xffffffffu, acc.x, off);
        acc.y += __shfl_xor_sync(0xffffffffu, acc.y, off);
        acc.z += __shfl_xor_sync(0xffffffffu, acc.z, off);
        acc.w += __shfl_xor_sync(0xffffffffu, acc.w, off);
    }

    if (sub == 0) {
        float inv = 1.0f / l;
        float4 o = make_float4(acc.x * inv, acc.y * inv, acc.z * inv, acc.w * inv);
        *(float4*)(out + qi * 256 + head * 32 + dq) = o;
    }
}

// ---------------------------------------------------------------------------
extern "C" void kernel_launch(void* const* d_in, const int* in_sizes, int n_in,
                              void* d_out, int out_size)
{
    const float* cur_f  = (const float*)d_in[0];
    const float* hist_f = (const float*)d_in[1];
    const float* cur_c  = (const float*)d_in[2];
    const float* hist_c = (const float*)d_in[3];
    const float* Wq = (const float*)d_in[4];
    const float* bq = (const float*)d_in[5];
    const float* Wk = (const float*)d_in[6];
    const float* bk = (const float*)d_in[7];
    const float* Wv = (const float*)d_in[8];
    const float* bv = (const float*)d_in[9];
    const float* Wo = (const float*)d_in[10];
    const float* bo = (const float*)d_in[11];
    float* out = (float*)d_out;

    float *pq, *pk, *pv, *patt;
    cudaGetSymbolAddress((void**)&pq,   g_q);
    cudaGetSymbolAddress((void**)&pk,   g_k);
    cudaGetSymbolAddress((void**)&pv,   g_v);
    cudaGetSymbolAddress((void**)&patt, g_att);

    dim3 gqkv(NQ / 64, FDIM / 64, 3);
    dim3 gg(NQ / 64, FDIM / 64);

    gemm_qkv_kernel<<<gqkv, 256>>>(cur_f, hist_f,
                                   Wq, bq, pq,
                                   Wk, bk, pk,
                                   Wv, bv, pv);

    attn_kernel<<<NQ, 256>>>(cur_c, hist_c, patt);

    gemm_bias_kernel<<<gg, 256>>>(patt, Wo, bo, out);
}

// round 4
// speedup vs baseline: 1.8899x; 1.0739x over previous
#include <cuda_runtime.h>
#include <math_constants.h>

#define NQ   4096
#define NK   4096
#define FDIM 256
#define RADIUS2 9.0f
#define MAXN 128     // per-warp neighbor capacity over its 512-key range
#define QPC  8       // queries per CTA (spatially sorted)
#define NCELL 512    // 8x8x8 cells of size 2.0

__device__ float g_q[NQ * FDIM];
__device__ float g_k[NK * FDIM];
__device__ float g_v[NK * FDIM];
__device__ float g_att[NQ * FDIM];
__device__ int   g_sorted[NQ];

// ---------------------------------------------------------------------------
// Single-block spatial counting sort of queries by Morton cell code.
// Deterministic OUTPUT: within-cell order varies by atomics, but each query's
// attention result is computed independently and written to out[qi].
// ---------------------------------------------------------------------------
__global__ void __launch_bounds__(512)
sort_kernel(const float* __restrict__ cq)
{
    __shared__ int  scnt[NCELL];
    __shared__ int  soff[NCELL];
    __shared__ short qcell[NQ];
    __shared__ int  wsum[16];

    const int t = threadIdx.x;
    scnt[t] = 0;
    __syncthreads();

    for (int q = t; q < NQ; q += 512) {
        int cx = (int)(cq[3 * q + 0] * 0.5f); cx = cx < 0 ? 0 : (cx > 7 ? 7 : cx);
        int cy = (int)(cq[3 * q + 1] * 0.5f); cy = cy < 0 ? 0 : (cy > 7 ? 7 : cy);
        int cz = (int)(cq[3 * q + 2] * 0.5f); cz = cz < 0 ? 0 : (cz > 7 ? 7 : cz);
        int m = 0;
        #pragma unroll
        for (int bbit = 0; bbit < 3; bbit++) {
            m |= ((cx >> bbit) & 1) << (3 * bbit + 2);
            m |= ((cy >> bbit) & 1) << (3 * bbit + 1);
            m |= ((cz >> bbit) & 1) << (3 * bbit + 0);
        }
        qcell[q] = (short)m;
        atomicAdd(&scnt[m], 1);
    }
    __syncthreads();

    // exclusive scan over 512 counts: warp scans + warp-sum scan
    {
        const int lane = t & 31, w = t >> 5;
        int v = scnt[t];
        int x = v;
        #pragma unroll
        for (int off = 1; off < 32; off <<= 1) {
            int y = __shfl_up_sync(0xffffffffu, x, off);
            if (lane >= off) x += y;
        }
        if (lane == 31) wsum[w] = x;
        __syncthreads();
        if (t < 16) {
            int s = wsum[t];
            int xs = s;
            #pragma unroll
            for (int off = 1; off < 16; off <<= 1) {
                int y = __shfl_up_sync(0xffffu, xs, off);
                if (t >= off) xs += y;
            }
            wsum[t] = xs - s;   // exclusive warp base
        }
        __syncthreads();
        soff[t] = wsum[w] + x - v;   // exclusive
    }
    __syncthreads();

    scnt[t] = 0;   // reuse as cursor
    __syncthreads();

    for (int q = t; q < NQ; q += 512) {
        int cell = qcell[q];
        int pos = atomicAdd(&scnt[cell], 1);
        g_sorted[soff[cell] + pos] = q;
    }
}

// ---------------------------------------------------------------------------
// C[M,256] = A[M,256] @ W[256,256]^T + b.  128x64 tile, BK=16, 256 thr, 8x4/thr.
// ---------------------------------------------------------------------------
__device__ __forceinline__ void gemm_body(const float* __restrict__ A,
                                          const float* __restrict__ W,
                                          const float* __restrict__ b,
                                          float* __restrict__ C)
{
    __shared__ float As[16][132];   // [k][row], 132 keeps float4 slices 16B aligned
    __shared__ float Ws[16][68];    // [k][col]

    const int tid = threadIdx.x;
    const int m0 = blockIdx.x * 128;
    const int n0 = blockIdx.y * 64;

    const int arow = tid >> 2;          // 0..63 (and +64)
    const int akc  = (tid & 3) * 4;     // 0,4,8,12
    const int wrow = tid >> 2;          // 0..63
    const int wkc  = (tid & 3) * 4;

    const int ty = tid >> 4;            // 0..15 -> 8 rows each
    const int tx = tid & 15;            // 0..15 -> 4 cols each

    float acc[8][4] = {};

    for (int kt = 0; kt < 256; kt += 16) {
        float4 a0 = *(const float4*)(A + (m0 + arow) * 256 + kt + akc);
        float4 a1 = *(const float4*)(A + (m0 + arow + 64) * 256 + kt + akc);
        float4 wv = *(const float4*)(W + (n0 + wrow) * 256 + kt + wkc);
        As[akc + 0][arow] = a0.x; As[akc + 1][arow] = a0.y;
        As[akc + 2][arow] = a0.z; As[akc + 3][arow] = a0.w;
        As[akc + 0][arow + 64] = a1.x; As[akc + 1][arow + 64] = a1.y;
        As[akc + 2][arow + 64] = a1.z; As[akc + 3][arow + 64] = a1.w;
        Ws[wkc + 0][wrow] = wv.x; Ws[wkc + 1][wrow] = wv.y;
        Ws[wkc + 2][wrow] = wv.z; Ws[wkc + 3][wrow] = wv.w;
        __syncthreads();

        #pragma unroll
        for (int k = 0; k < 16; k++) {
            float4 alo = *(const float4*)&As[k][ty * 8];
            float4 ahi = *(const float4*)&As[k][ty * 8 + 4];
            float4 w   = *(const float4*)&Ws[k][tx * 4];
            float a8[8] = {alo.x, alo.y, alo.z, alo.w, ahi.x, ahi.y, ahi.z, ahi.w};
            float w4[4] = {w.x, w.y, w.z, w.w};
            #pragma unroll
            for (int i = 0; i < 8; i++)
                #pragma unroll
                for (int j = 0; j < 4; j++)
                    acc[i][j] = fmaf(a8[i], w4[j], acc[i][j]);
        }
        __syncthreads();
    }

    const float4 bb = *(const float4*)(b + n0 + tx * 4);
    #pragma unroll
    for (int i = 0; i < 8; i++) {
        float4 o = make_float4(acc[i][0] + bb.x, acc[i][1] + bb.y,
                               acc[i][2] + bb.z, acc[i][3] + bb.w);
        *(float4*)(C + (m0 + ty * 8 + i) * 256 + n0 + tx * 4) = o;
    }
}

__global__ void __launch_bounds__(256)
gemm_qkv_kernel(const float* __restrict__ curf,
                const float* __restrict__ histf,
                const float* __restrict__ Wq, const float* __restrict__ bq, float* __restrict__ Cq,
                const float* __restrict__ Wk, const float* __restrict__ bk, float* __restrict__ Ck,
                const float* __restrict__ Wv, const float* __restrict__ bv, float* __restrict__ Cv)
{
    const float *A, *W, *b; float *C;
    if (blockIdx.z == 0)      { A = curf;  W = Wq; b = bq; C = Cq; }
    else if (blockIdx.z == 1) { A = histf; W = Wk; b = bk; C = Ck; }
    else                      { A = histf; W = Wv; b = bv; C = Cv; }
    gemm_body(A, W, b, C);
}

__global__ void __launch_bounds__(256)
gemm_bias_kernel(const float* __restrict__ A,
                 const float* __restrict__ W,
                 const float* __restrict__ b,
                 float* __restrict__ C)
{
    gemm_body(A, W, b, C);
}

// ---------------------------------------------------------------------------
// Sparse masked attention. CTA = QPC spatially-sorted queries (L1 reuse).
// warp = head; phase 2: 8 lanes/neighbor, 4 neighbors/pass, NO online max
// (scores ~N(0,1), exp overflow-safe; softmax is shift-invariant).
// ---------------------------------------------------------------------------
__global__ void __launch_bounds__(256)
attn_kernel(const float* __restrict__ cq,
            const float* __restrict__ ck,
            const int* __restrict__ sorted,
            float* __restrict__ out)
{
    const int tid  = threadIdx.x;
    const int warp = tid >> 5;
    const int lane = tid & 31;

    __shared__ int nbr[8][MAXN];
    __shared__ int cnt[8];
    __shared__ int offs[9];
    __shared__ int list[8 * MAXN];

    const int head = warp;
    const int sub  = lane >> 3;          // neighbor slot 0..3
    const int dq   = (lane & 7) * 4;     // float4 dim offset within head
    const float* kb = g_k + head * 32 + dq;
    const float* vb = g_v + head * 32 + dq;

    for (int qq = 0; qq < QPC; qq++) {
        const int qi = sorted[blockIdx.x * QPC + qq];

        const float qx = cq[3 * qi + 0];
        const float qy = cq[3 * qi + 1];
        const float qz = cq[3 * qi + 2];

        // Phase 1: ballot-compact neighbor scan (deterministic, ascending)
        int c = 0;
        const int base0 = warp * 512;
        for (int base = base0; base < base0 + 512; base += 32) {
            int j = base + lane;
            float dx = qx - ck[3 * j + 0];
            float dy = qy - ck[3 * j + 1];
            float dz = qz - ck[3 * j + 2];
            bool pass = (dx * dx + dy * dy + dz * dz) <= RADIUS2;
            unsigned mk = __ballot_sync(0xffffffffu, pass);
            if (pass) {
                int pos = c + __popc(mk & ((1u << lane) - 1u));
                if (pos < MAXN) nbr[warp][pos] = j;
            }
            c += __popc(mk);
        }
        if (lane == 0) cnt[warp] = (c < MAXN) ? c : MAXN;
        __syncthreads();

        if (tid == 0) {
            int o = 0;
            #pragma unroll
            for (int w = 0; w < 8; w++) { offs[w] = o; o += cnt[w]; }
            offs[8] = o;
        }
        __syncthreads();

        {
            const int n = cnt[warp], o = offs[warp];
            for (int i = lane; i < n; i += 32) list[o + i] = nbr[warp][i];
        }
        __syncthreads();

        // Phase 2: no-max softmax, per-group partial l
        const int ntot = offs[8];
        const float4 qv = *(const float4*)(g_q + qi * 256 + head * 32 + dq);

        float l = 0.0f;
        float4 acc = make_float4(0.f, 0.f, 0.f, 0.f);

        #pragma unroll 2
        for (int base = 0; base < ntot; base += 4) {
            const int nb = ntot - base;           // >= 1
            int g = sub;
            if (g > nb - 1) g = nb - 1;           // clamp; zeroed below
            const int j = list[base + g];

            const float4 kv = *(const float4*)(kb + j * 256);
            float p = qv.x * kv.x;
            p = fmaf(qv.y, kv.y, p);
            p = fmaf(qv.z, kv.z, p);
            p = fmaf(qv.w, kv.w, p);
            p += __shfl_xor_sync(0xffffffffu, p, 1);
            p += __shfl_xor_sync(0xffffffffu, p, 2);
            p += __shfl_xor_sync(0xffffffffu, p, 4);

            float e = __expf(p * 0.17677669529663687f);   // 1/sqrt(32)
            if (sub > nb - 1) e = 0.0f;                   // mask duplicated slots

            l += e;
            const float4 vv = *(const float4*)(vb + j * 256);
            acc.x = fmaf(e, vv.x, acc.x);
            acc.y = fmaf(e, vv.y, acc.y);
            acc.z = fmaf(e, vv.z, acc.z);
            acc.w = fmaf(e, vv.w, acc.w);
        }

        // reduce across the 4 neighbor-slot groups
        #pragma unroll
        for (int off = 8; off <= 16; off <<= 1) {
            acc.x += __shfl_xor_sync(0xffffffffu, acc.x, off);
            acc.y += __shfl_xor_sync(0xffffffffu, acc.y, off);
            acc.z += __shfl_xor_sync(0xffffffffu, acc.z, off);
            acc.w += __shfl_xor_sync(0xffffffffu, acc.w, off);
            l     += __shfl_xor_sync(0xffffffffu, l, off);
        }

        if (sub == 0) {
            float inv = 1.0f / l;
            float4 o = make_float4(acc.x * inv, acc.y * inv, acc.z * inv, acc.w * inv);
            *(float4*)(out + qi * 256 + head * 32 + dq) = o;
        }
        __syncthreads();   // smem reuse for next query
    }
}

// ---------------------------------------------------------------------------
extern "C" void kernel_launch(void* const* d_in, const int* in_sizes, int n_in,
                              void* d_out, int out_size)
{
    const float* cur_f  = (const float*)d_in[0];
    const float* hist_f = (const float*)d_in[1];
    const float* cur_c  = (const float*)d_in[2];
    const float* hist_c = (const float*)d_in[3];
    const float* Wq = (const float*)d_in[4];
    const float* bq = (const float*)d_in[5];
    const float* Wk = (const float*)d_in[6];
    const float* bk = (const float*)d_in[7];
    const float* Wv = (const float*)d_in[8];
    const float* bv = (const float*)d_in[9];
    const float* Wo = (const float*)d_in[10];
    const float* bo = (const float*)d_in[11];
    float* out = (float*)d_out;

    float *pq, *pk, *pv, *patt;
    int *psorted;
    cudaGetSymbolAddress((void**)&pq,   g_q);
    cudaGetSymbolAddress((void**)&pk,   g_k);
    cudaGetSymbolAddress((void**)&pv,   g_v);
    cudaGetSymbolAddress((void**)&patt, g_att);
    cudaGetSymbolAddress((void**)&psorted, g_sorted);

    sort_kernel<<<1, 512>>>(cur_c);

    dim3 gqkv(NQ / 128, FDIM / 64, 3);
    gemm_qkv_kernel<<<gqkv, 256>>>(cur_f, hist_f,
                                   Wq, bq, pq,
                                   Wk, bk, pk,
                                   Wv, bv, pv);

    attn_kernel<<<NQ / QPC, 256>>>(cur_c, hist_c, psorted, patt);

    dim3 go(NQ / 128, FDIM / 64);
    gemm_bias_kernel<<<go, 256>>>(patt, Wo, bo, out);
}

// round 6
// speedup vs baseline: 2.0884x; 1.1050x over previous
#include <cuda_runtime.h>
#include <math_constants.h>
#include <cstdint>

#define NQ   4096
#define NK   4096
#define FDIM 256
#define RADIUS2 9.0f
#define MAXN 128
#define QPC  8
#define NCELL 512

__device__ float g_q[NQ * FDIM];
__device__ float g_k[NK * FDIM];
__device__ float g_v[NK * FDIM];
__device__ float g_att[NQ * FDIM];
__device__ int   g_sorted[NQ];

// ======================= 3xTF32 mma.sync GEMM =======================
__device__ __forceinline__ void split_tf32(float x, uint32_t& hi, uint32_t& lo) {
    uint32_t h;
    asm("cvt.rna.tf32.f32 %0, %1;" : "=r"(h) : "f"(x));
    float r = x - __uint_as_float(h);
    uint32_t l;
    asm("cvt.rna.tf32.f32 %0, %1;" : "=r"(l) : "f"(r));
    hi = h; lo = l;
}

__device__ __forceinline__ void mma_tf32(float* d, const uint32_t* a, const uint32_t* b) {
    asm volatile(
        "mma.sync.aligned.m16n8k8.row.col.f32.tf32.tf32.f32 "
        "{%0,%1,%2,%3}, {%4,%5,%6,%7}, {%8,%9}, {%0,%1,%2,%3};"
        : "+f"(d[0]), "+f"(d[1]), "+f"(d[2]), "+f"(d[3])
        : "r"(a[0]), "r"(a[1]), "r"(a[2]), "r"(a[3]), "r"(b[0]), "r"(b[1]));
}

// C[BM x 64] tile of C = A @ W^T + b.  A[M,256], W[256(out),256(in)] row-major.
// 256 threads, warp grid 4(M) x 2(N); warp tile (16*MFRAGS) x 32.
template<int MFRAGS>
__device__ __forceinline__ void gemm_tc_body(const float* __restrict__ A,
                                             const float* __restrict__ W,
                                             const float* __restrict__ b,
                                             float* __restrict__ C)
{
    constexpr int BM = 64 * MFRAGS;     // 128 or 64
    __shared__ float As[BM][36];
    __shared__ float Ws[64][36];

    const int tid   = threadIdx.x;
    const int wid   = tid >> 5;
    const int lane  = tid & 31;
    const int warpM = wid >> 1;          // 0..3
    const int warpN = wid & 1;           // 0..1
    const int m0 = blockIdx.x * BM;
    const int n0 = blockIdx.y * 64;

    const int qrow = lane >> 2;          // 0..7
    const int qk   = lane & 3;           // 0..3

    float acc[MFRAGS][4][4] = {};

    for (int kt = 0; kt < 256; kt += 32) {
        // load A chunk [BM x 32]
        #pragma unroll
        for (int i = 0; i < BM / 32; i++) {
            int f = tid + i * 256;
            int row = f >> 3, kq = (f & 7) * 4;
            float4 v = *(const float4*)(A + (size_t)(m0 + row) * 256 + kt + kq);
            As[row][kq + 0] = v.x; As[row][kq + 1] = v.y;
            As[row][kq + 2] = v.z; As[row][kq + 3] = v.w;
        }
        // load W chunk [64 x 32]
        #pragma unroll
        for (int i = 0; i < 2; i++) {
            int f = tid + i * 256;
            int row = f >> 3, kq = (f & 7) * 4;
            float4 v = *(const float4*)(W + (size_t)(n0 + row) * 256 + kt + kq);
            Ws[row][kq + 0] = v.x; Ws[row][kq + 1] = v.y;
            Ws[row][kq + 2] = v.z; Ws[row][kq + 3] = v.w;
        }
        __syncthreads();

        #pragma unroll
        for (int ks = 0; ks < 4; ks++) {
            const int k0 = ks * 8;

            uint32_t ah[MFRAGS][4], al[MFRAGS][4];
            #pragma unroll
            for (int mf = 0; mf < MFRAGS; mf++) {
                int r = warpM * (16 * MFRAGS) + mf * 16 + qrow;
                split_tf32(As[r][k0 + qk],          ah[mf][0], al[mf][0]);
                split_tf32(As[r + 8][k0 + qk],      ah[mf][1], al[mf][1]);
                split_tf32(As[r][k0 + qk + 4],      ah[mf][2], al[mf][2]);
                split_tf32(As[r + 8][k0 + qk + 4],  ah[mf][3], al[mf][3]);
            }

            #pragma unroll
            for (int nf = 0; nf < 4; nf++) {
                int cn = warpN * 32 + nf * 8 + qrow;
                uint32_t bh[2], bl[2];
                split_tf32(Ws[cn][k0 + qk],     bh[0], bl[0]);
                split_tf32(Ws[cn][k0 + qk + 4], bh[1], bl[1]);
                #pragma unroll
                for (int mf = 0; mf < MFRAGS; mf++) {
                    mma_tf32(acc[mf][nf], ah[mf], bh);   // hi*hi
                    mma_tf32(acc[mf][nf], ah[mf], bl);   // hi*lo
                    mma_tf32(acc[mf][nf], al[mf], bh);   // lo*hi
                }
            }
        }
        __syncthreads();
    }

    // epilogue: D frag rows (qrow, qrow+8), cols (2*qk, 2*qk+1)
    #pragma unroll
    for (int mf = 0; mf < MFRAGS; mf++) {
        int r0 = m0 + warpM * (16 * MFRAGS) + mf * 16 + qrow;
        #pragma unroll
        for (int nf = 0; nf < 4; nf++) {
            int c0 = n0 + warpN * 32 + nf * 8 + qk * 2;
            float b0 = b[c0], b1 = b[c0 + 1];
            *(float2*)(C + (size_t)r0 * 256 + c0) =
                make_float2(acc[mf][nf][0] + b0, acc[mf][nf][1] + b1);
            *(float2*)(C + (size_t)(r0 + 8) * 256 + c0) =
                make_float2(acc[mf][nf][2] + b0, acc[mf][nf][3] + b1);
        }
    }
}

__global__ void __launch_bounds__(256)
gemm_qkv_tc(const float* __restrict__ curf, const float* __restrict__ histf,
            const float* __restrict__ Wq, const float* __restrict__ bq, float* __restrict__ Cq,
            const float* __restrict__ Wk, const float* __restrict__ bk, float* __restrict__ Ck,
            const float* __restrict__ Wv, const float* __restrict__ bv, float* __restrict__ Cv)
{
    const float *A, *W, *b; float *C;
    if (blockIdx.z == 0)      { A = curf;  W = Wq; b = bq; C = Cq; }
    else if (blockIdx.z == 1) { A = histf; W = Wk; b = bk; C = Ck; }
    else                      { A = histf; W = Wv; b = bv; C = Cv; }
    gemm_tc_body<2>(A, W, b, C);
}

__global__ void __launch_bounds__(256)
gemm_o_tc(const float* __restrict__ A, const float* __restrict__ W,
          const float* __restrict__ b, float* __restrict__ C)
{
    gemm_tc_body<1>(A, W, b, C);
}

// ======================= spatial sort (unchanged) =======================
__global__ void __launch_bounds__(512)
sort_kernel(const float* __restrict__ cq)
{
    __shared__ int  scnt[NCELL];
    __shared__ int  soff[NCELL];
    __shared__ short qcell[NQ];
    __shared__ int  wsum[16];

    const int t = threadIdx.x;
    scnt[t] = 0;
    __syncthreads();

    for (int q = t; q < NQ; q += 512) {
        int cx = (int)(cq[3 * q + 0] * 0.5f); cx = cx < 0 ? 0 : (cx > 7 ? 7 : cx);
        int cy = (int)(cq[3 * q + 1] * 0.5f); cy = cy < 0 ? 0 : (cy > 7 ? 7 : cy);
        int cz = (int)(cq[3 * q + 2] * 0.5f); cz = cz < 0 ? 0 : (cz > 7 ? 7 : cz);
        int m = 0;
        #pragma unroll
        for (int bbit = 0; bbit < 3; bbit++) {
            m |= ((cx >> bbit) & 1) << (3 * bbit + 2);
            m |= ((cy >> bbit) & 1) << (3 * bbit + 1);
            m |= ((cz >> bbit) & 1) << (3 * bbit + 0);
        }
        qcell[q] = (short)m;
        atomicAdd(&scnt[m], 1);
    }
    __syncthreads();

    {
        const int lane = t & 31, w = t >> 5;
        int v = scnt[t];
        int x = v;
        #pragma unroll
        for (int off = 1; off < 32; off <<= 1) {
            int y = __shfl_up_sync(0xffffffffu, x, off);
            if (lane >= off) x += y;
        }
        if (lane == 31) wsum[w] = x;
        __syncthreads();
        if (t < 16) {
            int s = wsum[t];
            int xs = s;
            #pragma unroll
            for (int off = 1; off < 16; off <<= 1) {
                int y = __shfl_up_sync(0xffffu, xs, off);
                if (t >= off) xs += y;
            }
            wsum[t] = xs - s;
        }
        __syncthreads();
        soff[t] = wsum[w] + x - v;
    }
    __syncthreads();

    scnt[t] = 0;
    __syncthreads();

    for (int q = t; q < NQ; q += 512) {
        int cell = qcell[q];
        int pos = atomicAdd(&scnt[cell], 1);
        g_sorted[soff[cell] + pos] = q;
    }
}

// ======================= sparse attention (unchanged) =======================
__global__ void __launch_bounds__(256)
attn_kernel(const float* __restrict__ cq,
            const float* __restrict__ ck,
            const int* __restrict__ sorted,
            float* __restrict__ out)
{
    const int tid  = threadIdx.x;
    const int warp = tid >> 5;
    const int lane = tid & 31;

    __shared__ int nbr[8][MAXN];
    __shared__ int cnt[8];
    __shared__ int offs[9];
    __shared__ int list[8 * MAXN];

    const int head = warp;
    const int sub  = lane >> 3;
    const int dq   = (lane & 7) * 4;
    const float* kb = g_k + head * 32 + dq;
    const float* vb = g_v + head * 32 + dq;

    for (int qq = 0; qq < QPC; qq++) {
        const int qi = sorted[blockIdx.x * QPC + qq];

        const float qx = cq[3 * qi + 0];
        const float qy = cq[3 * qi + 1];
        const float qz = cq[3 * qi + 2];

        int c = 0;
        const int base0 = warp * 512;
        for (int base = base0; base < base0 + 512; base += 32) {
            int j = base + lane;
            float dx = qx - ck[3 * j + 0];
            float dy = qy - ck[3 * j + 1];
            float dz = qz - ck[3 * j + 2];
            bool pass = (dx * dx + dy * dy + dz * dz) <= RADIUS2;
            unsigned mk = __ballot_sync(0xffffffffu, pass);
            if (pass) {
                int pos = c + __popc(mk & ((1u << lane) - 1u));
                if (pos < MAXN) nbr[warp][pos] = j;
            }
            c += __popc(mk);
        }
        if (lane == 0) cnt[warp] = (c < MAXN) ? c : MAXN;
        __syncthreads();

        if (tid == 0) {
            int o = 0;
            #pragma unroll
            for (int w = 0; w < 8; w++) { offs[w] = o; o += cnt[w]; }
            offs[8] = o;
        }
        __syncthreads();

        {
            const int n = cnt[warp], o = offs[warp];
            for (int i = lane; i < n; i += 32) list[o + i] = nbr[warp][i];
        }
        __syncthreads();

        const int ntot = offs[8];
        const float4 qv = *(const float4*)(g_q + qi * 256 + head * 32 + dq);

        float l = 0.0f;
        float4 acc = make_float4(0.f, 0.f, 0.f, 0.f);

        #pragma unroll 2
        for (int base = 0; base < ntot; base += 4) {
            const int nb = ntot - base;
            int g = sub;
            if (g > nb - 1) g = nb - 1;
            const int j = list[base + g];

            const float4 kv = *(const float4*)(kb + j * 256);
            float p = qv.x * kv.x;
            p = fmaf(qv.y, kv.y, p);
            p = fmaf(qv.z, kv.z, p);
            p = fmaf(qv.w, kv.w, p);
            p += __shfl_xor_sync(0xffffffffu, p, 1);
            p += __shfl_xor_sync(0xffffffffu, p, 2);
            p += __shfl_xor_sync(0xffffffffu, p, 4);

            float e = __expf(p * 0.17677669529663687f);
            if (sub > nb - 1) e = 0.0f;

            l += e;
            const float4 vv = *(const float4*)(vb + j * 256);
            acc.x = fmaf(e, vv.x, acc.x);
            acc.y = fmaf(e, vv.y, acc.y);
            acc.z = fmaf(e, vv.z, acc.z);
            acc.w = fmaf(e, vv.w, acc.w);
        }

        #pragma unroll
        for (int off = 8; off <= 16; off <<= 1) {
            acc.x += __shfl_xor_sync(0xffffffffu, acc.x, off);
            acc.y += __shfl_xor_sync(0xffffffffu, acc.y, off);
            acc.z += __shfl_xor_sync(0xffffffffu, acc.z, off);
            acc.w += __shfl_xor_sync(0xffffffffu, acc.w, off);
            l     += __shfl_xor_sync(0xffffffffu, l, off);
        }

        if (sub == 0) {
            float inv = 1.0f / l;
            float4 o = make_float4(acc.x * inv, acc.y * inv, acc.z * inv, acc.w * inv);
            *(float4*)(out + qi * 256 + head * 32 + dq) = o;
        }
        __syncthreads();
    }
}

// ---------------------------------------------------------------------------
extern "C" void kernel_launch(void* const* d_in, const int* in_sizes, int n_in,
                              void* d_out, int out_size)
{
    const float* cur_f  = (const float*)d_in[0];
    const float* hist_f = (const float*)d_in[1];
    const float* cur_c  = (const float*)d_in[2];
    const float* hist_c = (const float*)d_in[3];
    const float* Wq = (const float*)d_in[4];
    const float* bq = (const float*)d_in[5];
    const float* Wk = (const float*)d_in[6];
    const float* bk = (const float*)d_in[7];
    const float* Wv = (const float*)d_in[8];
    const float* bv = (const float*)d_in[9];
    const float* Wo = (const float*)d_in[10];
    const float* bo = (const float*)d_in[11];
    float* out = (float*)d_out;

    float *pq, *pk, *pv, *patt;
    int *psorted;
    cudaGetSymbolAddress((void**)&pq,   g_q);
    cudaGetSymbolAddress((void**)&pk,   g_k);
    cudaGetSymbolAddress((void**)&pv,   g_v);
    cudaGetSymbolAddress((void**)&patt, g_att);
    cudaGetSymbolAddress((void**)&psorted, g_sorted);

    sort_kernel<<<1, 512>>>(cur_c);

    dim3 gqkv(NQ / 128, FDIM / 64, 3);
    gemm_qkv_tc<<<gqkv, 256>>>(cur_f, hist_f,
                               Wq, bq, pq,
                               Wk, bk, pk,
                               Wv, bv, pv);

    attn_kernel<<<NQ / QPC, 256>>>(cur_c, hist_c, psorted, patt);

    dim3 go(NQ / 64, FDIM / 64);
    gemm_o_tc<<<go, 256>>>(patt, Wo, bo, out);
}